// round 6
// baseline (speedup 1.0000x reference)
#include <cuda_runtime.h>
#include <cuda_fp16.h>
#include <cstdint>

#define Bn    32
#define Cn    256
#define HWn   1024
#define NROWS 32768
#define Kn    1024
#define NTENS 8388608

// ---------------- scratch (device globals; no allocation allowed) ----------
__device__ __align__(16) __half g_Ah[NROWS * Cn];     // 16MB fp16 x (transposed)
__device__ __align__(16) __half g_Eh[Kn * Cn];        // 0.5MB fp16 emb
__device__ __align__(16) float  g_xt[NROWS * Cn];     // 32MB fp32 x transposed
__device__ float  g_sx[NROWS];
__device__ float  g_se[Kn];
__device__ unsigned long long g_best[NROWS];
__device__ uint32_t g_cand[NROWS * 32];
__device__ int    g_ccount;
__device__ int    g_fullcnt;
__device__ int    g_fullrows[NROWS];
__device__ double g_loss;

// proxy quantization: q = floor((p + 0.8) * 40000), step 2.5e-5
#define QSCALE 40000.0f
#define QOFS   0.8f
#define QWIN   26            // 6.5e-4 window in q-steps
#define ROWCAP 32

// ---------------- PTX helpers ----------------------------------------------
__device__ __forceinline__ uint32_t cvta_s(const void* p) {
    return (uint32_t)__cvta_generic_to_shared(p);
}
__device__ __forceinline__ void cp16(uint32_t dst, const void* src) {
    asm volatile("cp.async.cg.shared.global [%0], [%1], 16;"
                 :: "r"(dst), "l"(src) : "memory");
}
__device__ __forceinline__ void cp_commit() {
    asm volatile("cp.async.commit_group;" ::: "memory");
}
template <int N> __device__ __forceinline__ void cp_wait() {
    asm volatile("cp.async.wait_group %0;" :: "n"(N) : "memory");
}
__device__ __forceinline__ void ldsm4(uint32_t* r, uint32_t a) {
    asm volatile("ldmatrix.sync.aligned.m8n8.x4.shared.b16 {%0,%1,%2,%3},[%4];"
                 : "=r"(r[0]), "=r"(r[1]), "=r"(r[2]), "=r"(r[3]) : "r"(a));
}
__device__ __forceinline__ void mma16816(float* c, const uint32_t* a, const uint32_t* b) {
    asm volatile(
        "mma.sync.aligned.m16n8k16.row.col.f32.f16.f16.f32 "
        "{%0,%1,%2,%3},{%4,%5,%6,%7},{%8,%9},{%0,%1,%2,%3};"
        : "+f"(c[0]), "+f"(c[1]), "+f"(c[2]), "+f"(c[3])
        : "r"(a[0]), "r"(a[1]), "r"(a[2]), "r"(a[3]), "r"(b[0]), "r"(b[1]));
}

// ---------------------------------------------------------------------------
// Prep 1: emb -> fp16 + se (fp64->fp32); reset counters.
// ---------------------------------------------------------------------------
__global__ void k_prepe(const float* __restrict__ emb) {
    int k = blockIdx.x * 256 + threadIdx.x;
    if (k == 0) { g_loss = 0.0; g_ccount = 0; g_fullcnt = 0; }
    if (k >= Kn) return;
    const float* e = emb + (size_t)k * Cn;
    double s = 0.0;
    for (int g = 0; g < 32; g++) {
        float4 v0 = *(const float4*)(e + g * 8);
        float4 v1 = *(const float4*)(e + g * 8 + 4);
        float vv[8] = {v0.x, v0.y, v0.z, v0.w, v1.x, v1.y, v1.z, v1.w};
        __align__(16) __half hb[8];
        #pragma unroll
        for (int i = 0; i < 8; i++) {
            float v = vv[i];
            s += (double)v * (double)v;
            hb[i] = __float2half_rn(v);
        }
        *(uint4*)&g_Eh[(size_t)k * Cn + g * 8] = *(uint4*)hb;
    }
    g_se[k] = (float)s;
}

// ---------------------------------------------------------------------------
// Prep 2: x [B,C,H,W] -> fp16 transposed + fp32 transposed + sx per row.
// ---------------------------------------------------------------------------
__global__ __launch_bounds__(256) void k_split(const float* __restrict__ x) {
    __shared__ float  xs[256 * 33];
    __shared__ double ps[8][32];
    int blk = blockIdx.x;
    int b   = blk >> 5;
    int hw0 = (blk & 31) * 32;
    int tid = threadIdx.x;

    const float* xb = x + (size_t)b * (Cn * HWn) + hw0;
    #pragma unroll
    for (int t = 0; t < 8; t++) {
        int idx = tid + t * 256;
        int c = idx >> 3, g = idx & 7;
        float4 v = *(const float4*)(xb + (size_t)c * HWn + g * 4);
        xs[c * 33 + g * 4 + 0] = v.x;
        xs[c * 33 + g * 4 + 1] = v.y;
        xs[c * 33 + g * 4 + 2] = v.z;
        xs[c * 33 + g * 4 + 3] = v.w;
    }
    __syncthreads();

    int hw = tid & 31;
    int cs = tid >> 5;
    size_t n = (size_t)b * HWn + hw0 + hw;
    double s = 0.0;
    #pragma unroll 1
    for (int g = 0; g < 4; g++) {
        __align__(16) __half hb[8];
        __align__(16) float  fb[8];
        #pragma unroll
        for (int i = 0; i < 8; i++) {
            int c = cs * 32 + g * 8 + i;
            float v = xs[c * 33 + hw];
            s += (double)v * (double)v;
            hb[i] = __float2half_rn(v);
            fb[i] = v;
        }
        size_t o = n * Cn + cs * 32 + g * 8;
        *(uint4*)&g_Ah[o] = *(uint4*)hb;
        *(uint4*)&g_xt[o]     = *(uint4*)fb;
        *(uint4*)&g_xt[o + 4] = *(uint4*)(fb + 4);
    }
    ps[cs][hw] = s;
    __syncthreads();
    if (tid < 32) {
        double t = 0.0;
        #pragma unroll
        for (int j = 0; j < 8; j++) t += ps[j][tid];
        g_sx[(size_t)b * HWn + hw0 + tid] = (float)t;
    }
}

// ---------------------------------------------------------------------------
// Fused pruning GEMM + select. CTA: 64 rows x 1024 codes, fp16, K=256.
// q proxies live in smem; per-warp min + window-select emits candidates.
// ---------------------------------------------------------------------------
#define SA_OFF   0                      // 4 stages x 8KB = 32KB
#define SB_OFF   32768                  // 2 x 16KB = 32KB
#define SQ_OFF   65536                  // 64 rows x 2064B = 132096
#define QPITCH   2064                   // (1024+8) u16 per row
#define SES_OFF  (SQ_OFF + 64 * QPITCH) // 197632
#define SM_TOTAL (SES_OFF + 4096)       // 201728

__global__ __launch_bounds__(256, 1) void k_mma() {
    extern __shared__ char sm[];
    const uint32_t smem = cvta_s(sm);
    float* ses = (float*)(sm + SES_OFF);

    const int tid  = threadIdx.x;
    const int lane = tid & 31;
    const int wid  = tid >> 5;
    const int wm   = wid & 1;      // 2 warps over M (32 rows each)
    const int wn   = wid >> 1;     // 4 warps over N (32 codes each)
    const int row0 = blockIdx.x * 64;

    for (int i = tid; i < Kn; i += 256) ses[i] = g_se[i];

    // ---- preload A: 4 k-stages x 64 rows x 128B (one cp group) ----
    #pragma unroll
    for (int t = 0; t < 8; t++) {
        int idx = tid + t * 256;
        int st = idx >> 9;
        int r  = (idx >> 3) & 63;
        int kc = idx & 7;
        uint32_t bo = (uint32_t)(r * 128 + kc * 16);
        cp16(smem + SA_OFF + st * 8192 + (bo ^ ((bo >> 3) & 0x70)),
             g_Ah + (size_t)(row0 + r) * Cn + st * 64 + kc * 8);
    }
    cp_commit();

    #define ISSUEB(T) do {                                                    \
        int _t = (T);                                                         \
        int _cb = _t >> 2, _s = _t & 3;                                       \
        const __half* _gb = g_Eh + (size_t)(_cb * 128) * Cn + _s * 64;        \
        uint32_t _b = smem + SB_OFF + (uint32_t)(_t & 1) * 16384;             \
        _Pragma("unroll")                                                     \
        for (int _tt = 0; _tt < 4; _tt++) {                                   \
            int _idx = tid + _tt * 256;                                       \
            int _r = _idx >> 3, _kc = _idx & 7;                               \
            uint32_t _bo = (uint32_t)(_r * 128 + _kc * 16);                   \
            cp16(_b + (_bo ^ ((_bo >> 3) & 0x70)),                            \
                 _gb + (size_t)_r * Cn + _kc * 8);                            \
        }                                                                     \
        cp_commit();                                                          \
    } while (0)

    ISSUEB(0);

    const int arow0 = wm * 32 + (lane & 15);
    const int akofs = (lane >> 4);
    const int bnofs = ((lane >> 4) << 3) + (lane & 7);
    const int bkofs = ((lane >> 3) & 1);

    float acc[2][4][4];
    #pragma unroll
    for (int i = 0; i < 2; i++)
        #pragma unroll
        for (int j = 0; j < 4; j++)
            #pragma unroll
            for (int c = 0; c < 4; c++) acc[i][j][c] = 0.f;

    for (int t = 0; t < 32; t++) {
        __syncthreads();
        if (t + 1 < 32) { ISSUEB(t + 1); cp_wait<1>(); }
        else           cp_wait<0>();
        __syncthreads();

        const int s = t & 3;
        const uint32_t sA = smem + SA_OFF + (uint32_t)s * 8192;
        const uint32_t sB = smem + SB_OFF + (uint32_t)(t & 1) * 16384;

        #pragma unroll
        for (int ks = 0; ks < 4; ks++) {
            uint32_t af[2][4], bf[2][4];
            #pragma unroll
            for (int i = 0; i < 2; i++) {
                int r = arow0 + i * 16;
                int kc = ks * 2 + akofs;
                ldsm4(af[i], sA + r * 128 + ((kc ^ (r & 7)) << 4));
            }
            #pragma unroll
            for (int p = 0; p < 2; p++) {
                int n = wn * 32 + p * 16 + bnofs;
                int kc = ks * 2 + bkofs;
                ldsm4(bf[p], sB + n * 128 + ((kc ^ (n & 7)) << 4));
            }
            #pragma unroll
            for (int i = 0; i < 2; i++)
                #pragma unroll
                for (int j = 0; j < 4; j++)
                    mma16816(acc[i][j], af[i], &bf[j >> 1][(j & 1) * 2]);
        }

        if (s == 3) {   // end of code-block cb: emit q proxies to smem
            const int cb = t >> 2;
            uint32_t* qsm = (uint32_t*)(sm + SQ_OFF);
            #pragma unroll
            for (int i = 0; i < 2; i++) {
                #pragma unroll
                for (int j = 0; j < 4; j++) {
                    int ncode = cb * 128 + wn * 32 + j * 8 + (lane & 3) * 2;
                    uint32_t qv[4];
                    #pragma unroll
                    for (int c = 0; c < 4; c++) {
                        float p = __fmaf_rn(-2.0f, acc[i][j][c], ses[ncode + (c & 1)]);
                        float qf = (p + QOFS) * QSCALE;
                        qf = fminf(fmaxf(qf, 0.f), 65535.f);
                        qv[c] = (uint32_t)qf;
                        acc[i][j][c] = 0.f;
                    }
                    int rl = wm * 32 + i * 16 + (lane >> 2);   // rows rl, rl+8
                    int col = (ncode >> 1);                    // u32 column
                    qsm[rl * (QPITCH / 4) + col]       = qv[0] | (qv[1] << 16);
                    qsm[(rl + 8) * (QPITCH / 4) + col] = qv[2] | (qv[3] << 16);
                }
            }
        }
    }
    #undef ISSUEB
    __syncthreads();

    // ---- in-CTA selection: each warp owns 8 rows ----
    for (int rr = 0; rr < 8; rr++) {
        const int rowl = wid * 8 + rr;
        const int row  = row0 + rowl;
        const uint32_t* qr = (const uint32_t*)(sm + SQ_OFF) + rowl * (QPITCH / 4);

        uint32_t v[16];
        #pragma unroll
        for (int c4 = 0; c4 < 16; c4++) v[c4] = qr[lane + 32 * c4];

        uint32_t mn = 0xffffu;
        #pragma unroll
        for (int c4 = 0; c4 < 16; c4++) {
            uint32_t lo = v[c4] & 0xffffu, hi = v[c4] >> 16;
            mn = min(mn, min(lo, hi));
        }
        #pragma unroll
        for (int o = 16; o; o >>= 1)
            mn = min(mn, __shfl_xor_sync(0xffffffffu, mn, o));

        const uint32_t thr = mn + QWIN;

        int cnt = 0;
        #pragma unroll
        for (int c4 = 0; c4 < 16; c4++) {
            if ((v[c4] & 0xffffu) <= thr) cnt++;
            if ((v[c4] >> 16)    <= thr) cnt++;
        }
        int pfx = cnt;
        #pragma unroll
        for (int o = 1; o < 32; o <<= 1) {
            int u = __shfl_up_sync(0xffffffffu, pfx, o);
            if (lane >= o) pfx += u;
        }
        int total = __shfl_sync(0xffffffffu, pfx, 31);
        pfx -= cnt;

        if (total <= ROWCAP) {
            int base = 0;
            if (lane == 0 && total > 0) base = atomicAdd(&g_ccount, total);
            base = __shfl_sync(0xffffffffu, base, 0);
            int o = 0;
            #pragma unroll
            for (int c4 = 0; c4 < 16; c4++) {
                int m = lane + 32 * c4;    // u32 index -> codes 2m, 2m+1
                if ((v[c4] & 0xffffu) <= thr)
                    g_cand[base + pfx + (o++)] = ((uint32_t)row << 10) | (2 * m);
                if ((v[c4] >> 16) <= thr)
                    g_cand[base + pfx + (o++)] = ((uint32_t)row << 10) | (2 * m + 1);
            }
        } else if (lane == 0) {
            int fi = atomicAdd(&g_fullcnt, 1);
            g_fullrows[fi] = row;
        }
        if (lane == 0) g_best[row] = ~0ull;
    }
}

// ---------------------------------------------------------------------------
// Exact resolution: sequential fp32 dot per candidate (proven arithmetic).
// ---------------------------------------------------------------------------
__global__ __launch_bounds__(256) void k_exact(const float* __restrict__ emb) {
    const int total = g_ccount;
    for (int i = blockIdx.x * 256 + threadIdx.x; i < total; i += gridDim.x * 256) {
        uint32_t rc = g_cand[i];
        int row = rc >> 10, code = rc & 1023;
        const float* xr = g_xt + (size_t)row * Cn;
        const float* er = emb  + (size_t)code * Cn;
        float acc = 0.f;
        #pragma unroll 8
        for (int c = 0; c < Cn; c++) acc = fmaf(xr[c], er[c], acc);
        float D = __fsub_rn(__fadd_rn(g_sx[row], g_se[code]),
                            __fmul_rn(2.0f, acc));
        unsigned long long key =
            ((unsigned long long)__float_as_uint(D) << 32) | (unsigned)code;
        atomicMin(&g_best[row], key);
    }
}

// ---------------------------------------------------------------------------
// Safety net: full exact argmin for overflow rows (expected zero).
// ---------------------------------------------------------------------------
__global__ __launch_bounds__(256) void k_full(const float* __restrict__ emb) {
    __shared__ float xs[256];
    __shared__ unsigned long long bk;
    const int tid = threadIdx.x;
    const int nfull = g_fullcnt;
    for (int fi = blockIdx.x; fi < nfull; fi += gridDim.x) {
        int row = g_fullrows[fi];
        xs[tid] = g_xt[(size_t)row * Cn + tid];
        if (tid == 0) bk = ~0ull;
        __syncthreads();
        float sx = g_sx[row];
        #pragma unroll 1
        for (int kq = 0; kq < 4; kq++) {
            int k = kq * 256 + tid;
            const float* er = emb + (size_t)k * Cn;
            float acc = 0.f;
            #pragma unroll 8
            for (int c = 0; c < Cn; c++) acc = fmaf(xs[c], er[c], acc);
            float D = __fsub_rn(__fadd_rn(sx, g_se[k]), __fmul_rn(2.0f, acc));
            unsigned long long key =
                ((unsigned long long)__float_as_uint(D) << 32) | (unsigned)k;
            atomicMin(&bk, key);
        }
        __syncthreads();
        if (tid == 0) atomicMin(&g_best[row], bk);
        __syncthreads();
    }
}

// ---------------------------------------------------------------------------
// Output: gather codes, write [B,C,H,W], accumulate MSE.
// ---------------------------------------------------------------------------
__global__ __launch_bounds__(256)
void k_output(const float* __restrict__ x, const float* __restrict__ emb,
              float* __restrict__ out, int write_tensor) {
    int blk = blockIdx.x;
    int b   = blk >> 4;
    int hw0 = (blk & 15) * 64;
    int tid = threadIdx.x;
    int h4  = tid & 15;
    int cgv = tid >> 4;
    int hw  = hw0 + h4 * 4;
    int n0  = b * HWn + hw;
    int i0 = (int)(g_best[n0]     & 0xffffffffu);
    int i1 = (int)(g_best[n0 + 1] & 0xffffffffu);
    int i2 = (int)(g_best[n0 + 2] & 0xffffffffu);
    int i3 = (int)(g_best[n0 + 3] & 0xffffffffu);
    const float* xb = x   + (size_t)b * (Cn * HWn) + hw;
    float*       ob = out + (size_t)b * (Cn * HWn) + hw;

    float accl = 0.f;
    #pragma unroll 4
    for (int cc = 0; cc < 16; cc++) {
        int c = cgv * 16 + cc;
        float q0 = emb[i0 * Cn + c];
        float q1 = emb[i1 * Cn + c];
        float q2 = emb[i2 * Cn + c];
        float q3 = emb[i3 * Cn + c];
        float4 xv = *(const float4*)&xb[c * HWn];
        float d0 = q0 - xv.x, d1 = q1 - xv.y, d2 = q2 - xv.z, d3 = q3 - xv.w;
        accl += d0 * d0 + d1 * d1 + d2 * d2 + d3 * d3;
        if (write_tensor) {
            float4 qv = make_float4(q0, q1, q2, q3);
            *(float4*)&ob[c * HWn] = qv;
        }
    }
    __shared__ float red[256];
    red[tid] = accl;
    __syncthreads();
    for (int s = 128; s; s >>= 1) {
        if (tid < s) red[tid] += red[tid + s];
        __syncthreads();
    }
    if (tid == 0) atomicAdd(&g_loss, (double)red[0]);
}

__global__ void k_finalize(float* out, int pos) {
    out[pos] = (float)(1.25 * g_loss / (double)NTENS);
}

// ---------------------------------------------------------------------------
extern "C" void kernel_launch(void* const* d_in, const int* in_sizes, int n_in,
                              void* d_out, int out_size) {
    const float* x   = (const float*)d_in[0];
    const float* emb = (const float*)d_in[1];
    float* out = (float*)d_out;

    cudaFuncSetAttribute(k_mma, cudaFuncAttributeMaxDynamicSharedMemorySize, SM_TOTAL);

    k_prepe<<<4, 256>>>(emb);
    k_split<<<1024, 256>>>(x);
    k_mma<<<NROWS / 64, 256, SM_TOTAL>>>();
    k_exact<<<256, 256>>>(emb);
    k_full<<<64, 256>>>(emb);

    int write_tensor = (out_size >= NTENS) ? 1 : 0;
    k_output<<<512, 256>>>(x, emb, out, write_tensor);

    if (out_size == NTENS + 1)      k_finalize<<<1, 1>>>(out, NTENS);
    else if (out_size == 1)         k_finalize<<<1, 1>>>(out, 0);
}

// round 7
// speedup vs baseline: 1.1529x; 1.1529x over previous
#include <cuda_runtime.h>
#include <cuda_fp16.h>
#include <cstdint>

#define Bn    32
#define Cn    256
#define HWn   1024
#define NROWS 32768
#define Kn    1024
#define NTENS 8388608

// ---------------- scratch (device globals; no allocation allowed) ----------
__device__ __align__(16) __half g_Ah[NROWS * Cn];     // 16MB fp16 x (transposed)
__device__ __align__(16) __half g_Eh[Kn * Cn];        // 0.5MB fp16 emb
__device__ __align__(16) float  g_xt[NROWS * Cn];     // 32MB fp32 x transposed
__device__ __align__(16) uint32_t g_q[NROWS * 512];   // 64MB u16 proxy (packed)
__device__ float  g_sx[NROWS];
__device__ float  g_se[Kn];
__device__ unsigned long long g_best[NROWS];
__device__ uint32_t g_cand[NROWS * 16];
__device__ int    g_ccount;
__device__ int    g_fullcnt;
__device__ int    g_fullrows[NROWS];
__device__ double g_loss;

// proxy quantization: q = floor((p + 0.8) * 40000), step 2.5e-5
#define QSCALE 40000.0f
#define QOFS   0.8f
#define QWIN   26            // 6.5e-4 window in q-steps

// ---------------- PTX helpers ----------------------------------------------
__device__ __forceinline__ uint32_t cvta_s(const void* p) {
    return (uint32_t)__cvta_generic_to_shared(p);
}
__device__ __forceinline__ void cp16(uint32_t dst, const void* src) {
    asm volatile("cp.async.cg.shared.global [%0], [%1], 16;"
                 :: "r"(dst), "l"(src) : "memory");
}
__device__ __forceinline__ void cp_commit() {
    asm volatile("cp.async.commit_group;" ::: "memory");
}
template <int N> __device__ __forceinline__ void cp_wait() {
    asm volatile("cp.async.wait_group %0;" :: "n"(N) : "memory");
}
__device__ __forceinline__ void ldsm4(uint32_t* r, uint32_t a) {
    asm volatile("ldmatrix.sync.aligned.m8n8.x4.shared.b16 {%0,%1,%2,%3},[%4];"
                 : "=r"(r[0]), "=r"(r[1]), "=r"(r[2]), "=r"(r[3]) : "r"(a));
}
__device__ __forceinline__ void mma16816(float* c, const uint32_t* a, const uint32_t* b) {
    asm volatile(
        "mma.sync.aligned.m16n8k16.row.col.f32.f16.f16.f32 "
        "{%0,%1,%2,%3},{%4,%5,%6,%7},{%8,%9},{%0,%1,%2,%3};"
        : "+f"(c[0]), "+f"(c[1]), "+f"(c[2]), "+f"(c[3])
        : "r"(a[0]), "r"(a[1]), "r"(a[2]), "r"(a[3]), "r"(b[0]), "r"(b[1]));
}

// ---------------------------------------------------------------------------
// Prep 1: emb -> fp16 + se (fp64->fp32); reset counters.
// ---------------------------------------------------------------------------
__global__ void k_prepe(const float* __restrict__ emb) {
    int k = blockIdx.x * 256 + threadIdx.x;
    if (k == 0) { g_loss = 0.0; g_ccount = 0; g_fullcnt = 0; }
    if (k >= Kn) return;
    const float* e = emb + (size_t)k * Cn;
    double s = 0.0;
    for (int g = 0; g < 32; g++) {
        float4 v0 = *(const float4*)(e + g * 8);
        float4 v1 = *(const float4*)(e + g * 8 + 4);
        float vv[8] = {v0.x, v0.y, v0.z, v0.w, v1.x, v1.y, v1.z, v1.w};
        __align__(16) __half hb[8];
        #pragma unroll
        for (int i = 0; i < 8; i++) {
            float v = vv[i];
            s += (double)v * (double)v;
            hb[i] = __float2half_rn(v);
        }
        *(uint4*)&g_Eh[(size_t)k * Cn + g * 8] = *(uint4*)hb;
    }
    g_se[k] = (float)s;
}

// ---------------------------------------------------------------------------
// Prep 2: x [B,C,H,W] -> fp16 transposed + fp32 transposed + sx per row.
// ---------------------------------------------------------------------------
__global__ __launch_bounds__(256) void k_split(const float* __restrict__ x) {
    __shared__ float  xs[256 * 33];
    __shared__ double ps[8][32];
    int blk = blockIdx.x;
    int b   = blk >> 5;
    int hw0 = (blk & 31) * 32;
    int tid = threadIdx.x;

    const float* xb = x + (size_t)b * (Cn * HWn) + hw0;
    #pragma unroll
    for (int t = 0; t < 8; t++) {
        int idx = tid + t * 256;
        int c = idx >> 3, g = idx & 7;
        float4 v = *(const float4*)(xb + (size_t)c * HWn + g * 4);
        xs[c * 33 + g * 4 + 0] = v.x;
        xs[c * 33 + g * 4 + 1] = v.y;
        xs[c * 33 + g * 4 + 2] = v.z;
        xs[c * 33 + g * 4 + 3] = v.w;
    }
    __syncthreads();

    int hw = tid & 31;
    int cs = tid >> 5;
    size_t n = (size_t)b * HWn + hw0 + hw;
    double s = 0.0;
    #pragma unroll 1
    for (int g = 0; g < 4; g++) {
        __align__(16) __half hb[8];
        __align__(16) float  fb[8];
        #pragma unroll
        for (int i = 0; i < 8; i++) {
            int c = cs * 32 + g * 8 + i;
            float v = xs[c * 33 + hw];
            s += (double)v * (double)v;
            hb[i] = __float2half_rn(v);
            fb[i] = v;
        }
        size_t o = n * Cn + cs * 32 + g * 8;
        *(uint4*)&g_Ah[o] = *(uint4*)hb;
        *(uint4*)&g_xt[o]     = *(uint4*)fb;
        *(uint4*)&g_xt[o + 4] = *(uint4*)(fb + 4);
    }
    ps[cs][hw] = s;
    __syncthreads();
    if (tid < 32) {
        double t = 0.0;
        #pragma unroll
        for (int j = 0; j < 8; j++) t += ps[j][tid];
        g_sx[(size_t)b * HWn + hw0 + tid] = (float)t;
    }
}

// ---------------------------------------------------------------------------
// Pruning GEMM: fp16, K=256. CTA: 128 rows x (8 blocks of 128 codes).
// A tile (64KB, 4 k-stages) resident; B double-buffered (2x16KB).
// Emits u16 proxy q = quant(se - 2*dot) to gmem.   (round-5 proven code)
// ---------------------------------------------------------------------------
#define SA_OFF   0
#define SB_OFF   65536
#define SES_OFF  (65536 + 32768)
#define SM_TOTAL (SES_OFF + 4096)   // 102400

__global__ __launch_bounds__(256, 2) void k_mma() {
    extern __shared__ char sm[];
    const uint32_t smem = cvta_s(sm);
    float* ses = (float*)(sm + SES_OFF);

    const int tid  = threadIdx.x;
    const int lane = tid & 31;
    const int wid  = tid >> 5;
    const int wm   = wid & 3;
    const int wn   = wid >> 2;
    const int row0 = blockIdx.x * 128;

    for (int i = tid; i < Kn; i += 256) ses[i] = g_se[i];

    // ---- preload A: 4 k-stages x 128 rows x 128B (one cp group) ----
    {
        #pragma unroll
        for (int t = 0; t < 16; t++) {
            int idx = tid + t * 256;
            int st = idx >> 10;
            int r  = (idx >> 3) & 127;
            int kc = idx & 7;
            uint32_t bo = (uint32_t)(r * 128 + kc * 16);
            cp16(smem + SA_OFF + st * 16384 + (bo ^ ((bo >> 3) & 0x70)),
                 g_Ah + (size_t)(row0 + r) * Cn + st * 64 + kc * 8);
        }
        cp_commit();
    }

    #define ISSUEB(T) do {                                                    \
        int _t = (T);                                                         \
        int _cb = _t >> 2, _s = _t & 3;                                       \
        const __half* _gb = g_Eh + (size_t)(_cb * 128) * Cn + _s * 64;        \
        uint32_t _b = smem + SB_OFF + (uint32_t)(_t & 1) * 16384;             \
        _Pragma("unroll")                                                     \
        for (int _tt = 0; _tt < 4; _tt++) {                                   \
            int _idx = tid + _tt * 256;                                       \
            int _r = _idx >> 3, _kc = _idx & 7;                               \
            uint32_t _bo = (uint32_t)(_r * 128 + _kc * 16);                   \
            cp16(_b + (_bo ^ ((_bo >> 3) & 0x70)),                            \
                 _gb + (size_t)_r * Cn + _kc * 8);                            \
        }                                                                     \
        cp_commit();                                                          \
    } while (0)

    ISSUEB(0);

    const int arow0 = wm * 32 + (lane & 15);
    const int akofs = (lane >> 4);
    const int bnofs = ((lane >> 4) << 3) + (lane & 7);
    const int bkofs = ((lane >> 3) & 1);

    float acc[2][8][4];
    #pragma unroll
    for (int i = 0; i < 2; i++)
        #pragma unroll
        for (int j = 0; j < 8; j++)
            #pragma unroll
            for (int c = 0; c < 4; c++) acc[i][j][c] = 0.f;

    for (int t = 0; t < 32; t++) {
        __syncthreads();                 // all warps done with prior buffers
        if (t + 1 < 32) { ISSUEB(t + 1); cp_wait<1>(); }
        else           cp_wait<0>();
        __syncthreads();

        const int s = t & 3;
        const uint32_t sA = smem + SA_OFF + (uint32_t)s * 16384;
        const uint32_t sB = smem + SB_OFF + (uint32_t)(t & 1) * 16384;

        #pragma unroll
        for (int ks = 0; ks < 4; ks++) {
            uint32_t af[2][4], bf[4][4];
            #pragma unroll
            for (int i = 0; i < 2; i++) {
                int r = arow0 + i * 16;
                int kc = ks * 2 + akofs;
                ldsm4(af[i], sA + r * 128 + ((kc ^ (r & 7)) << 4));
            }
            #pragma unroll
            for (int p = 0; p < 4; p++) {
                int n = wn * 64 + p * 16 + bnofs;
                int kc = ks * 2 + bkofs;
                ldsm4(bf[p], sB + n * 128 + ((kc ^ (n & 7)) << 4));
            }
            #pragma unroll
            for (int i = 0; i < 2; i++)
                #pragma unroll
                for (int j = 0; j < 8; j++)
                    mma16816(acc[i][j], af[i], &bf[j >> 1][(j & 1) * 2]);
        }

        if (s == 3) {   // end of code-block cb: emit proxies, reset acc
            const int cb = t >> 2;
            #pragma unroll
            for (int i = 0; i < 2; i++) {
                #pragma unroll
                for (int j = 0; j < 8; j++) {
                    int ncode = cb * 128 + wn * 64 + j * 8 + (lane & 3) * 2;
                    uint32_t qv[4];
                    #pragma unroll
                    for (int c = 0; c < 4; c++) {
                        float p = __fmaf_rn(-2.0f, acc[i][j][c], ses[ncode + (c & 1)]);
                        float qf = (p + QOFS) * QSCALE;
                        qf = fminf(fmaxf(qf, 0.f), 65535.f);
                        qv[c] = (uint32_t)qf;
                        acc[i][j][c] = 0.f;
                    }
                    int ra = row0 + wm * 32 + i * 16 + (lane >> 2);
                    uint32_t col = (uint32_t)(cb * 64 + wn * 32 + j * 4 + (lane & 3));
                    g_q[(size_t)ra * 512 + col]         = qv[0] | (qv[1] << 16);
                    g_q[(size_t)(ra + 8) * 512 + col]   = qv[2] | (qv[3] << 16);
                }
            }
        }
    }
    #undef ISSUEB
}

// ---------------------------------------------------------------------------
// Select: per row (warp): min proxy, push candidates within QWIN.
// ---------------------------------------------------------------------------
__global__ __launch_bounds__(256) void k_select() {
    const int tid  = threadIdx.x;
    const int lane = tid & 31;
    const int row  = blockIdx.x * 8 + (tid >> 5);

    const uint4* qr = (const uint4*)(g_q + (size_t)row * 512);
    uint4 v[4];
    #pragma unroll
    for (int c4 = 0; c4 < 4; c4++) v[c4] = qr[lane + 32 * c4];

    uint32_t mn = 0xffffu;
    #pragma unroll
    for (int c4 = 0; c4 < 4; c4++) {
        uint32_t w[4] = {v[c4].x, v[c4].y, v[c4].z, v[c4].w};
        #pragma unroll
        for (int k = 0; k < 4; k++) {
            uint32_t lo = w[k] & 0xffffu, hi = w[k] >> 16;
            mn = min(mn, min(lo, hi));
        }
    }
    #pragma unroll
    for (int o = 16; o; o >>= 1)
        mn = min(mn, __shfl_xor_sync(0xffffffffu, mn, o));

    const uint32_t thr = mn + QWIN;

    int cnt = 0;
    #pragma unroll
    for (int c4 = 0; c4 < 4; c4++) {
        uint32_t w[4] = {v[c4].x, v[c4].y, v[c4].z, v[c4].w};
        #pragma unroll
        for (int k = 0; k < 4; k++) {
            if ((w[k] & 0xffffu) <= thr) cnt++;
            if ((w[k] >> 16)    <= thr) cnt++;
        }
    }
    int pfx = cnt;
    #pragma unroll
    for (int o = 1; o < 32; o <<= 1) {
        int u = __shfl_up_sync(0xffffffffu, pfx, o);
        if (lane >= o) pfx += u;
    }
    int total = __shfl_sync(0xffffffffu, pfx, 31);
    pfx -= cnt;

    if (total <= 16) {
        int base = 0;
        if (lane == 0 && total > 0) base = atomicAdd(&g_ccount, total);
        base = __shfl_sync(0xffffffffu, base, 0);
        int o = 0;
        #pragma unroll
        for (int c4 = 0; c4 < 4; c4++) {
            uint32_t w[4] = {v[c4].x, v[c4].y, v[c4].z, v[c4].w};
            #pragma unroll
            for (int k = 0; k < 4; k++) {
                int m = 4 * (lane + 32 * c4) + k;   // u32 index -> codes 2m,2m+1
                if ((w[k] & 0xffffu) <= thr)
                    g_cand[base + pfx + (o++)] = ((uint32_t)row << 10) | (2 * m);
                if ((w[k] >> 16) <= thr)
                    g_cand[base + pfx + (o++)] = ((uint32_t)row << 10) | (2 * m + 1);
            }
        }
    } else {
        if (lane == 0) {
            int fi = atomicAdd(&g_fullcnt, 1);
            g_fullrows[fi] = row;
        }
    }
    if (lane == 0) g_best[row] = ~0ull;
}

// ---------------------------------------------------------------------------
// Exact resolution: sequential fp32 dot per candidate — identical rounding
// order to round 5 (ascending c), but float4 loads (4x fewer L1 sectors)
// and a bigger grid for latency hiding.
// ---------------------------------------------------------------------------
__global__ __launch_bounds__(256) void k_exact(const float* __restrict__ emb) {
    const int total = g_ccount;
    for (int i = blockIdx.x * 256 + threadIdx.x; i < total; i += gridDim.x * 256) {
        uint32_t rc = g_cand[i];
        int row = rc >> 10, code = rc & 1023;
        const float4* xr = (const float4*)(g_xt + (size_t)row * Cn);
        const float4* er = (const float4*)(emb  + (size_t)code * Cn);
        float acc = 0.f;
        #pragma unroll 8
        for (int c = 0; c < Cn / 4; c++) {
            float4 xv = __ldg(xr + c);
            float4 ev = __ldg(er + c);
            acc = fmaf(xv.x, ev.x, acc);
            acc = fmaf(xv.y, ev.y, acc);
            acc = fmaf(xv.z, ev.z, acc);
            acc = fmaf(xv.w, ev.w, acc);
        }
        float D = __fsub_rn(__fadd_rn(g_sx[row], g_se[code]),
                            __fmul_rn(2.0f, acc));
        unsigned long long key =
            ((unsigned long long)__float_as_uint(D) << 32) | (unsigned)code;
        atomicMin(&g_best[row], key);
    }
}

// ---------------------------------------------------------------------------
// Safety net: full exact argmin for overflow rows (expected zero).
// ---------------------------------------------------------------------------
__global__ __launch_bounds__(256) void k_full(const float* __restrict__ emb) {
    __shared__ float xs[256];
    __shared__ unsigned long long bk;
    const int tid = threadIdx.x;
    const int nfull = g_fullcnt;
    for (int fi = blockIdx.x; fi < nfull; fi += gridDim.x) {
        int row = g_fullrows[fi];
        xs[tid] = g_xt[(size_t)row * Cn + tid];
        if (tid == 0) bk = ~0ull;
        __syncthreads();
        float sx = g_sx[row];
        #pragma unroll 1
        for (int kq = 0; kq < 4; kq++) {
            int k = kq * 256 + tid;
            const float4* er = (const float4*)(emb + (size_t)k * Cn);
            const float4* xv4 = (const float4*)xs;
            float acc = 0.f;
            #pragma unroll 8
            for (int c = 0; c < Cn / 4; c++) {
                float4 ev = __ldg(er + c);
                float4 xv = xv4[c];
                acc = fmaf(xv.x, ev.x, acc);
                acc = fmaf(xv.y, ev.y, acc);
                acc = fmaf(xv.z, ev.z, acc);
                acc = fmaf(xv.w, ev.w, acc);
            }
            float D = __fsub_rn(__fadd_rn(sx, g_se[k]), __fmul_rn(2.0f, acc));
            unsigned long long key =
                ((unsigned long long)__float_as_uint(D) << 32) | (unsigned)k;
            atomicMin(&bk, key);
        }
        __syncthreads();
        if (tid == 0) atomicMin(&g_best[row], bk);
        __syncthreads();
    }
}

// ---------------------------------------------------------------------------
// Output: gather codes, write [B,C,H,W], accumulate MSE.
// ---------------------------------------------------------------------------
__global__ __launch_bounds__(256)
void k_output(const float* __restrict__ x, const float* __restrict__ emb,
              float* __restrict__ out, int write_tensor) {
    int blk = blockIdx.x;
    int b   = blk >> 4;
    int hw0 = (blk & 15) * 64;
    int tid = threadIdx.x;
    int h4  = tid & 15;
    int cgv = tid >> 4;
    int hw  = hw0 + h4 * 4;
    int n0  = b * HWn + hw;
    int i0 = (int)(g_best[n0]     & 0xffffffffu);
    int i1 = (int)(g_best[n0 + 1] & 0xffffffffu);
    int i2 = (int)(g_best[n0 + 2] & 0xffffffffu);
    int i3 = (int)(g_best[n0 + 3] & 0xffffffffu);
    const float* xb = x   + (size_t)b * (Cn * HWn) + hw;
    float*       ob = out + (size_t)b * (Cn * HWn) + hw;

    float accl = 0.f;
    #pragma unroll 4
    for (int cc = 0; cc < 16; cc++) {
        int c = cgv * 16 + cc;
        float q0 = emb[i0 * Cn + c];
        float q1 = emb[i1 * Cn + c];
        float q2 = emb[i2 * Cn + c];
        float q3 = emb[i3 * Cn + c];
        float4 xv = *(const float4*)&xb[c * HWn];
        float d0 = q0 - xv.x, d1 = q1 - xv.y, d2 = q2 - xv.z, d3 = q3 - xv.w;
        accl += d0 * d0 + d1 * d1 + d2 * d2 + d3 * d3;
        if (write_tensor) {
            float4 qv = make_float4(q0, q1, q2, q3);
            *(float4*)&ob[c * HWn] = qv;
        }
    }
    __shared__ float red[256];
    red[tid] = accl;
    __syncthreads();
    for (int s = 128; s; s >>= 1) {
        if (tid < s) red[tid] += red[tid + s];
        __syncthreads();
    }
    if (tid == 0) atomicAdd(&g_loss, (double)red[0]);
}

__global__ void k_finalize(float* out, int pos) {
    out[pos] = (float)(1.25 * g_loss / (double)NTENS);
}

// ---------------------------------------------------------------------------
extern "C" void kernel_launch(void* const* d_in, const int* in_sizes, int n_in,
                              void* d_out, int out_size) {
    const float* x   = (const float*)d_in[0];
    const float* emb = (const float*)d_in[1];
    float* out = (float*)d_out;

    cudaFuncSetAttribute(k_mma, cudaFuncAttributeMaxDynamicSharedMemorySize, SM_TOTAL);

    k_prepe<<<4, 256>>>(emb);
    k_split<<<1024, 256>>>(x);
    k_mma<<<NROWS / 128, 256, SM_TOTAL>>>();
    k_select<<<NROWS / 8, 256>>>();
    k_exact<<<2048, 256>>>(emb);
    k_full<<<64, 256>>>(emb);

    int write_tensor = (out_size >= NTENS) ? 1 : 0;
    k_output<<<512, 256>>>(x, emb, out, write_tensor);

    if (out_size == NTENS + 1)      k_finalize<<<1, 1>>>(out, NTENS);
    else if (out_size == 1)         k_finalize<<<1, 1>>>(out, 0);
}

// round 8
// speedup vs baseline: 1.3116x; 1.1376x over previous
#include <cuda_runtime.h>
#include <cuda_fp16.h>
#include <cstdint>

#define Bn    32
#define Cn    256
#define HWn   1024
#define NROWS 32768
#define Kn    1024
#define NTENS 8388608

// ---------------- scratch (device globals; no allocation allowed) ----------
__device__ __align__(16) __half g_Ah[NROWS * Cn];     // 16MB fp16 x (transposed)
__device__ __align__(16) __half g_Eh[Kn * Cn];        // 0.5MB fp16 emb
__device__ __align__(16) float  g_xt[NROWS * Cn];     // 32MB fp32 x transposed
__device__ float  g_sx[NROWS];
__device__ float  g_se[Kn];
__device__ unsigned long long g_best[NROWS];
__device__ uint32_t g_cand[NROWS * 16];
__device__ int    g_ccount;
__device__ int    g_fullcnt;
__device__ int    g_fullrows[NROWS];
__device__ double g_loss;

// proxy quantization: q = floor((p + 0.8) * 40000), step 2.5e-5
#define QSCALE 40000.0f
#define QOFS   0.8f
#define QWIN   26u           // 6.5e-4 window in q-steps
#define CAP    16

// ---------------- PTX helpers ----------------------------------------------
__device__ __forceinline__ uint32_t cvta_s(const void* p) {
    return (uint32_t)__cvta_generic_to_shared(p);
}
__device__ __forceinline__ void cp16(uint32_t dst, const void* src) {
    asm volatile("cp.async.cg.shared.global [%0], [%1], 16;"
                 :: "r"(dst), "l"(src) : "memory");
}
__device__ __forceinline__ void cp_commit() {
    asm volatile("cp.async.commit_group;" ::: "memory");
}
template <int N> __device__ __forceinline__ void cp_wait() {
    asm volatile("cp.async.wait_group %0;" :: "n"(N) : "memory");
}
__device__ __forceinline__ void ldsm4(uint32_t* r, uint32_t a) {
    asm volatile("ldmatrix.sync.aligned.m8n8.x4.shared.b16 {%0,%1,%2,%3},[%4];"
                 : "=r"(r[0]), "=r"(r[1]), "=r"(r[2]), "=r"(r[3]) : "r"(a));
}
__device__ __forceinline__ void mma16816(float* c, const uint32_t* a, const uint32_t* b) {
    asm volatile(
        "mma.sync.aligned.m16n8k16.row.col.f32.f16.f16.f32 "
        "{%0,%1,%2,%3},{%4,%5,%6,%7},{%8,%9},{%0,%1,%2,%3};"
        : "+f"(c[0]), "+f"(c[1]), "+f"(c[2]), "+f"(c[3])
        : "r"(a[0]), "r"(a[1]), "r"(a[2]), "r"(a[3]), "r"(b[0]), "r"(b[1]));
}

// ---------------------------------------------------------------------------
// Prep 1: emb -> fp16 + se (fp64->fp32); reset counters.
// ---------------------------------------------------------------------------
__global__ void k_prepe(const float* __restrict__ emb) {
    int k = blockIdx.x * 256 + threadIdx.x;
    if (k == 0) { g_loss = 0.0; g_ccount = 0; g_fullcnt = 0; }
    if (k >= Kn) return;
    const float* e = emb + (size_t)k * Cn;
    double s = 0.0;
    for (int g = 0; g < 32; g++) {
        float4 v0 = *(const float4*)(e + g * 8);
        float4 v1 = *(const float4*)(e + g * 8 + 4);
        float vv[8] = {v0.x, v0.y, v0.z, v0.w, v1.x, v1.y, v1.z, v1.w};
        __align__(16) __half hb[8];
        #pragma unroll
        for (int i = 0; i < 8; i++) {
            float v = vv[i];
            s += (double)v * (double)v;
            hb[i] = __float2half_rn(v);
        }
        *(uint4*)&g_Eh[(size_t)k * Cn + g * 8] = *(uint4*)hb;
    }
    g_se[k] = (float)s;
}

// ---------------------------------------------------------------------------
// Prep 2: x [B,C,H,W] -> fp16 transposed + fp32 transposed + sx per row.
// ---------------------------------------------------------------------------
__global__ __launch_bounds__(256) void k_split(const float* __restrict__ x) {
    __shared__ float  xs[256 * 33];
    __shared__ double ps[8][32];
    int blk = blockIdx.x;
    int b   = blk >> 5;
    int hw0 = (blk & 31) * 32;
    int tid = threadIdx.x;

    const float* xb = x + (size_t)b * (Cn * HWn) + hw0;
    #pragma unroll
    for (int t = 0; t < 8; t++) {
        int idx = tid + t * 256;
        int c = idx >> 3, g = idx & 7;
        float4 v = *(const float4*)(xb + (size_t)c * HWn + g * 4);
        xs[c * 33 + g * 4 + 0] = v.x;
        xs[c * 33 + g * 4 + 1] = v.y;
        xs[c * 33 + g * 4 + 2] = v.z;
        xs[c * 33 + g * 4 + 3] = v.w;
    }
    __syncthreads();

    int hw = tid & 31;
    int cs = tid >> 5;
    size_t n = (size_t)b * HWn + hw0 + hw;
    double s = 0.0;
    #pragma unroll 1
    for (int g = 0; g < 4; g++) {
        __align__(16) __half hb[8];
        __align__(16) float  fb[8];
        #pragma unroll
        for (int i = 0; i < 8; i++) {
            int c = cs * 32 + g * 8 + i;
            float v = xs[c * 33 + hw];
            s += (double)v * (double)v;
            hb[i] = __float2half_rn(v);
            fb[i] = v;
        }
        size_t o = n * Cn + cs * 32 + g * 8;
        *(uint4*)&g_Ah[o] = *(uint4*)hb;
        *(uint4*)&g_xt[o]     = *(uint4*)fb;
        *(uint4*)&g_xt[o + 4] = *(uint4*)(fb + 4);
    }
    ps[cs][hw] = s;
    __syncthreads();
    if (tid < 32) {
        double t = 0.0;
        #pragma unroll
        for (int j = 0; j < 8; j++) t += ps[j][tid];
        g_sx[(size_t)b * HWn + hw0 + tid] = (float)t;
    }
}

// ---------------------------------------------------------------------------
// Fused pruning GEMM + incremental select. M=128 rows/CTA, 2 CTAs/SM.
// Per 128-code block: q -> smem running min + windowed candidate push
// (superset-safe: stale min only over-accepts). Final re-filter vs converged
// min reproduces the round-5/7 candidate set exactly.
// ---------------------------------------------------------------------------
#define SA_OFF    0
#define SB_OFF    65536
#define SES_OFF   (65536 + 32768)          // 98304, 4KB
#define SMIN_OFF  (SES_OFF + 4096)         // 102400, 512B
#define SCNT_OFF  (SMIN_OFF + 512)         // 102912, 512B
#define SLIST_OFF (SCNT_OFF + 512)         // 103424, 8KB
#define SM_TOTAL  (SLIST_OFF + 128 * CAP * 4)   // 111616

__global__ __launch_bounds__(256, 2) void k_mma() {
    extern __shared__ char sm[];
    const uint32_t smem = cvta_s(sm);
    float*    ses   = (float*)(sm + SES_OFF);
    uint32_t* smin  = (uint32_t*)(sm + SMIN_OFF);
    uint32_t* scnt  = (uint32_t*)(sm + SCNT_OFF);
    uint32_t* slist = (uint32_t*)(sm + SLIST_OFF);

    const int tid  = threadIdx.x;
    const int lane = tid & 31;
    const int wid  = tid >> 5;
    const int wm   = wid & 3;
    const int wn   = wid >> 2;
    const int row0 = blockIdx.x * 128;

    for (int i = tid; i < Kn; i += 256) ses[i] = g_se[i];
    if (tid < 128) { smin[tid] = 0xffffffffu; scnt[tid] = 0; }

    // ---- preload A: 4 k-stages x 128 rows x 128B (one cp group) ----
    {
        #pragma unroll
        for (int t = 0; t < 16; t++) {
            int idx = tid + t * 256;
            int st = idx >> 10;
            int r  = (idx >> 3) & 127;
            int kc = idx & 7;
            uint32_t bo = (uint32_t)(r * 128 + kc * 16);
            cp16(smem + SA_OFF + st * 16384 + (bo ^ ((bo >> 3) & 0x70)),
                 g_Ah + (size_t)(row0 + r) * Cn + st * 64 + kc * 8);
        }
        cp_commit();
    }

    #define ISSUEB(T) do {                                                    \
        int _t = (T);                                                         \
        int _cb = _t >> 2, _s = _t & 3;                                       \
        const __half* _gb = g_Eh + (size_t)(_cb * 128) * Cn + _s * 64;        \
        uint32_t _b = smem + SB_OFF + (uint32_t)(_t & 1) * 16384;             \
        _Pragma("unroll")                                                     \
        for (int _tt = 0; _tt < 4; _tt++) {                                   \
            int _idx = tid + _tt * 256;                                       \
            int _r = _idx >> 3, _kc = _idx & 7;                               \
            uint32_t _bo = (uint32_t)(_r * 128 + _kc * 16);                   \
            cp16(_b + (_bo ^ ((_bo >> 3) & 0x70)),                            \
                 _gb + (size_t)_r * Cn + _kc * 8);                            \
        }                                                                     \
        cp_commit();                                                          \
    } while (0)

    ISSUEB(0);

    const int arow0 = wm * 32 + (lane & 15);
    const int akofs = (lane >> 4);
    const int bnofs = ((lane >> 4) << 3) + (lane & 7);
    const int bkofs = ((lane >> 3) & 1);

    float acc[2][8][4];
    #pragma unroll
    for (int i = 0; i < 2; i++)
        #pragma unroll
        for (int j = 0; j < 8; j++)
            #pragma unroll
            for (int c = 0; c < 4; c++) acc[i][j][c] = 0.f;

    for (int t = 0; t < 32; t++) {
        __syncthreads();
        if (t + 1 < 32) { ISSUEB(t + 1); cp_wait<1>(); }
        else           cp_wait<0>();
        __syncthreads();

        const int s = t & 3;
        const uint32_t sA = smem + SA_OFF + (uint32_t)s * 16384;
        const uint32_t sB = smem + SB_OFF + (uint32_t)(t & 1) * 16384;

        #pragma unroll
        for (int ks = 0; ks < 4; ks++) {
            uint32_t af[2][4], bf[4][4];
            #pragma unroll
            for (int i = 0; i < 2; i++) {
                int r = arow0 + i * 16;
                int kc = ks * 2 + akofs;
                ldsm4(af[i], sA + r * 128 + ((kc ^ (r & 7)) << 4));
            }
            #pragma unroll
            for (int p = 0; p < 4; p++) {
                int n = wn * 64 + p * 16 + bnofs;
                int kc = ks * 2 + bkofs;
                ldsm4(bf[p], sB + n * 128 + ((kc ^ (n & 7)) << 4));
            }
            #pragma unroll
            for (int i = 0; i < 2; i++)
                #pragma unroll
                for (int j = 0; j < 8; j++)
                    mma16816(acc[i][j], af[i], &bf[j >> 1][(j & 1) * 2]);
        }

        if (s == 3) {   // end of code-block cb: q -> running min + push
            const int cb = t >> 2;
            uint32_t lm[2][2] = {{0xffffffffu, 0xffffffffu},
                                 {0xffffffffu, 0xffffffffu}};
            #pragma unroll
            for (int i = 0; i < 2; i++) {
                #pragma unroll
                for (int j = 0; j < 8; j++) {
                    int ncode = cb * 128 + wn * 64 + j * 8 + (lane & 3) * 2;
                    #pragma unroll
                    for (int c = 0; c < 4; c++) {
                        float p = __fmaf_rn(-2.0f, acc[i][j][c], ses[ncode + (c & 1)]);
                        float qf = (p + QOFS) * QSCALE;
                        qf = fminf(fmaxf(qf, 0.f), 65535.f);
                        uint32_t qv = (uint32_t)qf;
                        lm[i][c >> 1] = min(lm[i][c >> 1], qv);
                        acc[i][j][c] = __uint_as_float(qv);
                    }
                }
                #pragma unroll
                for (int h = 0; h < 2; h++)
                    atomicMin(&smin[wm * 32 + i * 16 + h * 8 + (lane >> 2)], lm[i][h]);
            }
            __syncthreads();
            #pragma unroll
            for (int i = 0; i < 2; i++)
                #pragma unroll
                for (int j = 0; j < 8; j++) {
                    int ncode = cb * 128 + wn * 64 + j * 8 + (lane & 3) * 2;
                    #pragma unroll
                    for (int c = 0; c < 4; c++) {
                        uint32_t qv = __float_as_uint(acc[i][j][c]);
                        int rl = wm * 32 + i * 16 + (c >> 1) * 8 + (lane >> 2);
                        if (qv <= smin[rl] + QWIN) {
                            uint32_t idx = atomicAdd(&scnt[rl], 1u);
                            if (idx < CAP)
                                slist[rl * CAP + idx] =
                                    (qv << 10) | (uint32_t)(ncode + (c & 1));
                        }
                        acc[i][j][c] = 0.f;
                    }
                }
        }
    }
    #undef ISSUEB

    // ---- final: re-filter lists vs converged min, emit candidates ----
    __syncthreads();
    if (tid < 128) {
        int row = row0 + tid;
        g_best[row] = ~0ull;
        uint32_t cnt = scnt[tid];
        if (cnt > CAP) {
            g_fullrows[atomicAdd(&g_fullcnt, 1)] = row;
        } else {
            uint32_t thr = smin[tid] + QWIN;
            uint32_t tmp[CAP];
            int o = 0;
            for (uint32_t e = 0; e < cnt; e++) {
                uint32_t v = slist[tid * CAP + e];
                if ((v >> 10) <= thr)
                    tmp[o++] = ((uint32_t)row << 10) | (v & 1023u);
            }
            int base = atomicAdd(&g_ccount, o);
            for (int e = 0; e < o; e++) g_cand[base + e] = tmp[e];
        }
    }
}

// ---------------------------------------------------------------------------
// Exact resolution: sequential fp32 dot per candidate (proven round-7 code).
// ---------------------------------------------------------------------------
__global__ __launch_bounds__(256) void k_exact(const float* __restrict__ emb) {
    const int total = g_ccount;
    for (int i = blockIdx.x * 256 + threadIdx.x; i < total; i += gridDim.x * 256) {
        uint32_t rc = g_cand[i];
        int row = rc >> 10, code = rc & 1023;
        const float4* xr = (const float4*)(g_xt + (size_t)row * Cn);
        const float4* er = (const float4*)(emb  + (size_t)code * Cn);
        float acc = 0.f;
        #pragma unroll 8
        for (int c = 0; c < Cn / 4; c++) {
            float4 xv = __ldg(xr + c);
            float4 ev = __ldg(er + c);
            acc = fmaf(xv.x, ev.x, acc);
            acc = fmaf(xv.y, ev.y, acc);
            acc = fmaf(xv.z, ev.z, acc);
            acc = fmaf(xv.w, ev.w, acc);
        }
        float D = __fsub_rn(__fadd_rn(g_sx[row], g_se[code]),
                            __fmul_rn(2.0f, acc));
        unsigned long long key =
            ((unsigned long long)__float_as_uint(D) << 32) | (unsigned)code;
        atomicMin(&g_best[row], key);
    }
}

// ---------------------------------------------------------------------------
// Safety net: full exact argmin for overflow rows (expected ~zero).
// ---------------------------------------------------------------------------
__global__ __launch_bounds__(256) void k_full(const float* __restrict__ emb) {
    __shared__ float xs[256];
    __shared__ unsigned long long bk;
    const int tid = threadIdx.x;
    const int nfull = g_fullcnt;
    for (int fi = blockIdx.x; fi < nfull; fi += gridDim.x) {
        int row = g_fullrows[fi];
        xs[tid] = g_xt[(size_t)row * Cn + tid];
        if (tid == 0) bk = ~0ull;
        __syncthreads();
        float sx = g_sx[row];
        #pragma unroll 1
        for (int kq = 0; kq < 4; kq++) {
            int k = kq * 256 + tid;
            const float4* er = (const float4*)(emb + (size_t)k * Cn);
            const float4* xv4 = (const float4*)xs;
            float acc = 0.f;
            #pragma unroll 8
            for (int c = 0; c < Cn / 4; c++) {
                float4 ev = __ldg(er + c);
                float4 xv = xv4[c];
                acc = fmaf(xv.x, ev.x, acc);
                acc = fmaf(xv.y, ev.y, acc);
                acc = fmaf(xv.z, ev.z, acc);
                acc = fmaf(xv.w, ev.w, acc);
            }
            float D = __fsub_rn(__fadd_rn(sx, g_se[k]), __fmul_rn(2.0f, acc));
            unsigned long long key =
                ((unsigned long long)__float_as_uint(D) << 32) | (unsigned)k;
            atomicMin(&bk, key);
        }
        __syncthreads();
        if (tid == 0) atomicMin(&g_best[row], bk);
        __syncthreads();
    }
}

// ---------------------------------------------------------------------------
// Output: gather codes, write [B,C,H,W], accumulate MSE.
// ---------------------------------------------------------------------------
__global__ __launch_bounds__(256)
void k_output(const float* __restrict__ x, const float* __restrict__ emb,
              float* __restrict__ out, int write_tensor) {
    int blk = blockIdx.x;
    int b   = blk >> 4;
    int hw0 = (blk & 15) * 64;
    int tid = threadIdx.x;
    int h4  = tid & 15;
    int cgv = tid >> 4;
    int hw  = hw0 + h4 * 4;
    int n0  = b * HWn + hw;
    int i0 = (int)(g_best[n0]     & 0xffffffffu);
    int i1 = (int)(g_best[n0 + 1] & 0xffffffffu);
    int i2 = (int)(g_best[n0 + 2] & 0xffffffffu);
    int i3 = (int)(g_best[n0 + 3] & 0xffffffffu);
    const float* xb = x   + (size_t)b * (Cn * HWn) + hw;
    float*       ob = out + (size_t)b * (Cn * HWn) + hw;

    float accl = 0.f;
    #pragma unroll 4
    for (int cc = 0; cc < 16; cc++) {
        int c = cgv * 16 + cc;
        float q0 = emb[i0 * Cn + c];
        float q1 = emb[i1 * Cn + c];
        float q2 = emb[i2 * Cn + c];
        float q3 = emb[i3 * Cn + c];
        float4 xv = *(const float4*)&xb[c * HWn];
        float d0 = q0 - xv.x, d1 = q1 - xv.y, d2 = q2 - xv.z, d3 = q3 - xv.w;
        accl += d0 * d0 + d1 * d1 + d2 * d2 + d3 * d3;
        if (write_tensor) {
            float4 qv = make_float4(q0, q1, q2, q3);
            *(float4*)&ob[c * HWn] = qv;
        }
    }
    __shared__ float red[256];
    red[tid] = accl;
    __syncthreads();
    for (int s = 128; s; s >>= 1) {
        if (tid < s) red[tid] += red[tid + s];
        __syncthreads();
    }
    if (tid == 0) atomicAdd(&g_loss, (double)red[0]);
}

__global__ void k_finalize(float* out, int pos) {
    out[pos] = (float)(1.25 * g_loss / (double)NTENS);
}

// ---------------------------------------------------------------------------
extern "C" void kernel_launch(void* const* d_in, const int* in_sizes, int n_in,
                              void* d_out, int out_size) {
    const float* x   = (const float*)d_in[0];
    const float* emb = (const float*)d_in[1];
    float* out = (float*)d_out;

    cudaFuncSetAttribute(k_mma, cudaFuncAttributeMaxDynamicSharedMemorySize, SM_TOTAL);

    k_prepe<<<4, 256>>>(emb);
    k_split<<<1024, 256>>>(x);
    k_mma<<<NROWS / 128, 256, SM_TOTAL>>>();
    k_exact<<<2048, 256>>>(emb);
    k_full<<<64, 256>>>(emb);

    int write_tensor = (out_size >= NTENS) ? 1 : 0;
    k_output<<<512, 256>>>(x, emb, out, write_tensor);

    if (out_size == NTENS + 1)      k_finalize<<<1, 1>>>(out, NTENS);
    else if (out_size == 1)         k_finalize<<<1, 1>>>(out, 0);
}

// round 9
// speedup vs baseline: 1.4730x; 1.1231x over previous
#include <cuda_runtime.h>
#include <cuda_fp16.h>
#include <cstdint>

#define Bn    32
#define Cn    256
#define HWn   1024
#define NROWS 32768
#define Kn    1024
#define NTENS 8388608

// ---------------- scratch (device globals; no allocation allowed) ----------
__device__ __align__(16) __half g_Ah[NROWS * Cn];     // 16MB fp16 x (transposed)
__device__ __align__(16) __half g_Eh[Kn * Cn];        // 0.5MB fp16 emb
__device__ __align__(16) float  g_xt[NROWS * Cn];     // 32MB fp32 x transposed
__device__ float  g_sx[NROWS];
__device__ float  g_se[Kn];
__device__ unsigned long long g_best[NROWS];
__device__ uint32_t g_cand[NROWS * 16];
__device__ int    g_ccount;
__device__ int    g_fullcnt;
__device__ int    g_fullrows[NROWS];
__device__ double g_loss;

// proxy quantization: q = floor((p + 0.8) * 40000), step 2.5e-5
#define QSCALE 40000.0f
#define QOFS   0.8f
#define QWIN   26u           // 6.5e-4 window in q-steps
#define CAP    16

// ---------------- PTX helpers ----------------------------------------------
__device__ __forceinline__ uint32_t cvta_s(const void* p) {
    return (uint32_t)__cvta_generic_to_shared(p);
}
__device__ __forceinline__ void cp16(uint32_t dst, const void* src) {
    asm volatile("cp.async.cg.shared.global [%0], [%1], 16;"
                 :: "r"(dst), "l"(src) : "memory");
}
__device__ __forceinline__ void cp_commit() {
    asm volatile("cp.async.commit_group;" ::: "memory");
}
template <int N> __device__ __forceinline__ void cp_wait() {
    asm volatile("cp.async.wait_group %0;" :: "n"(N) : "memory");
}
__device__ __forceinline__ void ldsm4(uint32_t* r, uint32_t a) {
    asm volatile("ldmatrix.sync.aligned.m8n8.x4.shared.b16 {%0,%1,%2,%3},[%4];"
                 : "=r"(r[0]), "=r"(r[1]), "=r"(r[2]), "=r"(r[3]) : "r"(a));
}
__device__ __forceinline__ void mma16816(float* c, const uint32_t* a, const uint32_t* b) {
    asm volatile(
        "mma.sync.aligned.m16n8k16.row.col.f32.f16.f16.f32 "
        "{%0,%1,%2,%3},{%4,%5,%6,%7},{%8,%9},{%0,%1,%2,%3};"
        : "+f"(c[0]), "+f"(c[1]), "+f"(c[2]), "+f"(c[3])
        : "r"(a[0]), "r"(a[1]), "r"(a[2]), "r"(a[3]), "r"(b[0]), "r"(b[1]));
}

// ---------------------------------------------------------------------------
// Prep 1: emb -> fp16 + se (fp64->fp32); reset counters.
// ---------------------------------------------------------------------------
__global__ void k_prepe(const float* __restrict__ emb) {
    int k = blockIdx.x * 256 + threadIdx.x;
    if (k == 0) { g_loss = 0.0; g_ccount = 0; g_fullcnt = 0; }
    if (k >= Kn) return;
    const float* e = emb + (size_t)k * Cn;
    double s = 0.0;
    for (int g = 0; g < 32; g++) {
        float4 v0 = *(const float4*)(e + g * 8);
        float4 v1 = *(const float4*)(e + g * 8 + 4);
        float vv[8] = {v0.x, v0.y, v0.z, v0.w, v1.x, v1.y, v1.z, v1.w};
        __align__(16) __half hb[8];
        #pragma unroll
        for (int i = 0; i < 8; i++) {
            float v = vv[i];
            s += (double)v * (double)v;
            hb[i] = __float2half_rn(v);
        }
        *(uint4*)&g_Eh[(size_t)k * Cn + g * 8] = *(uint4*)hb;
    }
    g_se[k] = (float)s;
}

// ---------------------------------------------------------------------------
// Prep 2: x [B,C,H,W] -> fp16 transposed + fp32 transposed + sx per row.
// ---------------------------------------------------------------------------
__global__ __launch_bounds__(256) void k_split(const float* __restrict__ x) {
    __shared__ float  xs[256 * 33];
    __shared__ double ps[8][32];
    int blk = blockIdx.x;
    int b   = blk >> 5;
    int hw0 = (blk & 31) * 32;
    int tid = threadIdx.x;

    const float* xb = x + (size_t)b * (Cn * HWn) + hw0;
    #pragma unroll
    for (int t = 0; t < 8; t++) {
        int idx = tid + t * 256;
        int c = idx >> 3, g = idx & 7;
        float4 v = *(const float4*)(xb + (size_t)c * HWn + g * 4);
        xs[c * 33 + g * 4 + 0] = v.x;
        xs[c * 33 + g * 4 + 1] = v.y;
        xs[c * 33 + g * 4 + 2] = v.z;
        xs[c * 33 + g * 4 + 3] = v.w;
    }
    __syncthreads();

    int hw = tid & 31;
    int cs = tid >> 5;
    size_t n = (size_t)b * HWn + hw0 + hw;
    double s = 0.0;
    #pragma unroll 1
    for (int g = 0; g < 4; g++) {
        __align__(16) __half hb[8];
        __align__(16) float  fb[8];
        #pragma unroll
        for (int i = 0; i < 8; i++) {
            int c = cs * 32 + g * 8 + i;
            float v = xs[c * 33 + hw];
            s += (double)v * (double)v;
            hb[i] = __float2half_rn(v);
            fb[i] = v;
        }
        size_t o = n * Cn + cs * 32 + g * 8;
        *(uint4*)&g_Ah[o] = *(uint4*)hb;
        *(uint4*)&g_xt[o]     = *(uint4*)fb;
        *(uint4*)&g_xt[o + 4] = *(uint4*)(fb + 4);
    }
    ps[cs][hw] = s;
    __syncthreads();
    if (tid < 32) {
        double t = 0.0;
        #pragma unroll
        for (int j = 0; j < 8; j++) t += ps[j][tid];
        g_sx[(size_t)b * HWn + hw0 + tid] = (float)t;
    }
}

// ---------------------------------------------------------------------------
// Fused pruning GEMM + incremental select. M=128 rows/CTA, 2 CTAs/SM.
// Final refilter: |set|==1 -> winner is certified, write g_best directly.
// ---------------------------------------------------------------------------
#define SA_OFF    0
#define SB_OFF    65536
#define SES_OFF   (65536 + 32768)          // 98304, 4KB
#define SMIN_OFF  (SES_OFF + 4096)         // 102400, 512B
#define SCNT_OFF  (SMIN_OFF + 512)         // 102912, 512B
#define SLIST_OFF (SCNT_OFF + 512)         // 103424, 8KB
#define SM_TOTAL  (SLIST_OFF + 128 * CAP * 4)   // 111616

__global__ __launch_bounds__(256, 2) void k_mma() {
    extern __shared__ char sm[];
    const uint32_t smem = cvta_s(sm);
    float*    ses   = (float*)(sm + SES_OFF);
    uint32_t* smin  = (uint32_t*)(sm + SMIN_OFF);
    uint32_t* scnt  = (uint32_t*)(sm + SCNT_OFF);
    uint32_t* slist = (uint32_t*)(sm + SLIST_OFF);

    const int tid  = threadIdx.x;
    const int lane = tid & 31;
    const int wid  = tid >> 5;
    const int wm   = wid & 3;
    const int wn   = wid >> 2;
    const int row0 = blockIdx.x * 128;

    for (int i = tid; i < Kn; i += 256) ses[i] = g_se[i];
    if (tid < 128) { smin[tid] = 0xffffffffu; scnt[tid] = 0; }

    // ---- preload A: 4 k-stages x 128 rows x 128B (one cp group) ----
    {
        #pragma unroll
        for (int t = 0; t < 16; t++) {
            int idx = tid + t * 256;
            int st = idx >> 10;
            int r  = (idx >> 3) & 127;
            int kc = idx & 7;
            uint32_t bo = (uint32_t)(r * 128 + kc * 16);
            cp16(smem + SA_OFF + st * 16384 + (bo ^ ((bo >> 3) & 0x70)),
                 g_Ah + (size_t)(row0 + r) * Cn + st * 64 + kc * 8);
        }
        cp_commit();
    }

    #define ISSUEB(T) do {                                                    \
        int _t = (T);                                                         \
        int _cb = _t >> 2, _s = _t & 3;                                       \
        const __half* _gb = g_Eh + (size_t)(_cb * 128) * Cn + _s * 64;        \
        uint32_t _b = smem + SB_OFF + (uint32_t)(_t & 1) * 16384;             \
        _Pragma("unroll")                                                     \
        for (int _tt = 0; _tt < 4; _tt++) {                                   \
            int _idx = tid + _tt * 256;                                       \
            int _r = _idx >> 3, _kc = _idx & 7;                               \
            uint32_t _bo = (uint32_t)(_r * 128 + _kc * 16);                   \
            cp16(_b + (_bo ^ ((_bo >> 3) & 0x70)),                            \
                 _gb + (size_t)_r * Cn + _kc * 8);                            \
        }                                                                     \
        cp_commit();                                                          \
    } while (0)

    ISSUEB(0);

    const int arow0 = wm * 32 + (lane & 15);
    const int akofs = (lane >> 4);
    const int bnofs = ((lane >> 4) << 3) + (lane & 7);
    const int bkofs = ((lane >> 3) & 1);

    float acc[2][8][4];
    #pragma unroll
    for (int i = 0; i < 2; i++)
        #pragma unroll
        for (int j = 0; j < 8; j++)
            #pragma unroll
            for (int c = 0; c < 4; c++) acc[i][j][c] = 0.f;

    for (int t = 0; t < 32; t++) {
        __syncthreads();
        if (t + 1 < 32) { ISSUEB(t + 1); cp_wait<1>(); }
        else           cp_wait<0>();
        __syncthreads();

        const int s = t & 3;
        const uint32_t sA = smem + SA_OFF + (uint32_t)s * 16384;
        const uint32_t sB = smem + SB_OFF + (uint32_t)(t & 1) * 16384;

        #pragma unroll
        for (int ks = 0; ks < 4; ks++) {
            uint32_t af[2][4], bf[4][4];
            #pragma unroll
            for (int i = 0; i < 2; i++) {
                int r = arow0 + i * 16;
                int kc = ks * 2 + akofs;
                ldsm4(af[i], sA + r * 128 + ((kc ^ (r & 7)) << 4));
            }
            #pragma unroll
            for (int p = 0; p < 4; p++) {
                int n = wn * 64 + p * 16 + bnofs;
                int kc = ks * 2 + bkofs;
                ldsm4(bf[p], sB + n * 128 + ((kc ^ (n & 7)) << 4));
            }
            #pragma unroll
            for (int i = 0; i < 2; i++)
                #pragma unroll
                for (int j = 0; j < 8; j++)
                    mma16816(acc[i][j], af[i], &bf[j >> 1][(j & 1) * 2]);
        }

        if (s == 3) {   // end of code-block cb: q -> running min + push
            const int cb = t >> 2;
            uint32_t lm[2][2] = {{0xffffffffu, 0xffffffffu},
                                 {0xffffffffu, 0xffffffffu}};
            #pragma unroll
            for (int i = 0; i < 2; i++) {
                #pragma unroll
                for (int j = 0; j < 8; j++) {
                    int ncode = cb * 128 + wn * 64 + j * 8 + (lane & 3) * 2;
                    #pragma unroll
                    for (int c = 0; c < 4; c++) {
                        float p = __fmaf_rn(-2.0f, acc[i][j][c], ses[ncode + (c & 1)]);
                        float qf = (p + QOFS) * QSCALE;
                        qf = fminf(fmaxf(qf, 0.f), 65535.f);
                        uint32_t qv = (uint32_t)qf;
                        lm[i][c >> 1] = min(lm[i][c >> 1], qv);
                        acc[i][j][c] = __uint_as_float(qv);
                    }
                }
                #pragma unroll
                for (int h = 0; h < 2; h++)
                    atomicMin(&smin[wm * 32 + i * 16 + h * 8 + (lane >> 2)], lm[i][h]);
            }
            __syncthreads();
            #pragma unroll
            for (int i = 0; i < 2; i++)
                #pragma unroll
                for (int j = 0; j < 8; j++) {
                    int ncode = cb * 128 + wn * 64 + j * 8 + (lane & 3) * 2;
                    #pragma unroll
                    for (int c = 0; c < 4; c++) {
                        uint32_t qv = __float_as_uint(acc[i][j][c]);
                        int rl = wm * 32 + i * 16 + (c >> 1) * 8 + (lane >> 2);
                        if (qv <= smin[rl] + QWIN) {
                            uint32_t idx = atomicAdd(&scnt[rl], 1u);
                            if (idx < CAP)
                                slist[rl * CAP + idx] =
                                    (qv << 10) | (uint32_t)(ncode + (c & 1));
                        }
                        acc[i][j][c] = 0.f;
                    }
                }
        }
    }
    #undef ISSUEB

    // ---- final: re-filter vs converged min; singleton rows resolved here ----
    __syncthreads();
    if (tid < 128) {
        int row = row0 + tid;
        uint32_t cnt = scnt[tid];
        if (cnt > CAP) {
            g_best[row] = ~0ull;
            g_fullrows[atomicAdd(&g_fullcnt, 1)] = row;
        } else {
            uint32_t thr = smin[tid] + QWIN;
            uint32_t tmp[CAP];
            int o = 0;
            for (uint32_t e = 0; e < cnt; e++) {
                uint32_t v = slist[tid * CAP + e];
                if ((v >> 10) <= thr)
                    tmp[o++] = ((uint32_t)row << 10) | (v & 1023u);
            }
            if (o == 1) {
                // certified: the lone window member IS the reference argmin
                g_best[row] = (unsigned long long)(tmp[0] & 1023u);
            } else {
                g_best[row] = ~0ull;
                int base = atomicAdd(&g_ccount, o);
                for (int e = 0; e < o; e++) g_cand[base + e] = tmp[e];
            }
        }
    }
}

// ---------------------------------------------------------------------------
// Exact resolution for multi-candidate rows. Candidate j -> block j%grid so
// the scattered-load latency spreads over all SMs.
// ---------------------------------------------------------------------------
__global__ __launch_bounds__(64) void k_exact(const float* __restrict__ emb) {
    const int total = g_ccount;
    for (int i = threadIdx.x * gridDim.x + blockIdx.x; i < total;
         i += gridDim.x * 64) {
        uint32_t rc = g_cand[i];
        int row = rc >> 10, code = rc & 1023;
        const float4* xr = (const float4*)(g_xt + (size_t)row * Cn);
        const float4* er = (const float4*)(emb  + (size_t)code * Cn);
        float acc = 0.f;
        #pragma unroll 8
        for (int c = 0; c < Cn / 4; c++) {
            float4 xv = __ldg(xr + c);
            float4 ev = __ldg(er + c);
            acc = fmaf(xv.x, ev.x, acc);
            acc = fmaf(xv.y, ev.y, acc);
            acc = fmaf(xv.z, ev.z, acc);
            acc = fmaf(xv.w, ev.w, acc);
        }
        float D = __fsub_rn(__fadd_rn(g_sx[row], g_se[code]),
                            __fmul_rn(2.0f, acc));
        unsigned long long key =
            ((unsigned long long)__float_as_uint(D) << 32) | (unsigned)code;
        atomicMin(&g_best[row], key);
    }
}

// ---------------------------------------------------------------------------
// Safety net: full exact argmin for overflow rows (expected ~zero).
// ---------------------------------------------------------------------------
__global__ __launch_bounds__(256) void k_full(const float* __restrict__ emb) {
    __shared__ float xs[256];
    __shared__ unsigned long long bk;
    const int tid = threadIdx.x;
    const int nfull = g_fullcnt;
    for (int fi = blockIdx.x; fi < nfull; fi += gridDim.x) {
        int row = g_fullrows[fi];
        xs[tid] = g_xt[(size_t)row * Cn + tid];
        if (tid == 0) bk = ~0ull;
        __syncthreads();
        float sx = g_sx[row];
        #pragma unroll 1
        for (int kq = 0; kq < 4; kq++) {
            int k = kq * 256 + tid;
            const float4* er = (const float4*)(emb + (size_t)k * Cn);
            const float4* xv4 = (const float4*)xs;
            float acc = 0.f;
            #pragma unroll 8
            for (int c = 0; c < Cn / 4; c++) {
                float4 ev = __ldg(er + c);
                float4 xv = xv4[c];
                acc = fmaf(xv.x, ev.x, acc);
                acc = fmaf(xv.y, ev.y, acc);
                acc = fmaf(xv.z, ev.z, acc);
                acc = fmaf(xv.w, ev.w, acc);
            }
            float D = __fsub_rn(__fadd_rn(sx, g_se[k]), __fmul_rn(2.0f, acc));
            unsigned long long key =
                ((unsigned long long)__float_as_uint(D) << 32) | (unsigned)k;
            atomicMin(&bk, key);
        }
        __syncthreads();
        if (tid == 0) atomicMin(&g_best[row], bk);
        __syncthreads();
    }
}

// ---------------------------------------------------------------------------
// Output: gather codes, write [B,C,H,W], accumulate MSE.
// ---------------------------------------------------------------------------
__global__ __launch_bounds__(256)
void k_output(const float* __restrict__ x, const float* __restrict__ emb,
              float* __restrict__ out, int write_tensor) {
    int blk = blockIdx.x;
    int b   = blk >> 4;
    int hw0 = (blk & 15) * 64;
    int tid = threadIdx.x;
    int h4  = tid & 15;
    int cgv = tid >> 4;
    int hw  = hw0 + h4 * 4;
    int n0  = b * HWn + hw;
    int i0 = (int)(g_best[n0]     & 0xffffffffu) & 1023;
    int i1 = (int)(g_best[n0 + 1] & 0xffffffffu) & 1023;
    int i2 = (int)(g_best[n0 + 2] & 0xffffffffu) & 1023;
    int i3 = (int)(g_best[n0 + 3] & 0xffffffffu) & 1023;
    const float* xb = x   + (size_t)b * (Cn * HWn) + hw;
    float*       ob = out + (size_t)b * (Cn * HWn) + hw;

    float accl = 0.f;
    #pragma unroll 4
    for (int cc = 0; cc < 16; cc++) {
        int c = cgv * 16 + cc;
        float q0 = emb[i0 * Cn + c];
        float q1 = emb[i1 * Cn + c];
        float q2 = emb[i2 * Cn + c];
        float q3 = emb[i3 * Cn + c];
        float4 xv = *(const float4*)&xb[c * HWn];
        float d0 = q0 - xv.x, d1 = q1 - xv.y, d2 = q2 - xv.z, d3 = q3 - xv.w;
        accl += d0 * d0 + d1 * d1 + d2 * d2 + d3 * d3;
        if (write_tensor) {
            float4 qv = make_float4(q0, q1, q2, q3);
            *(float4*)&ob[c * HWn] = qv;
        }
    }
    __shared__ float red[256];
    red[tid] = accl;
    __syncthreads();
    for (int s = 128; s; s >>= 1) {
        if (tid < s) red[tid] += red[tid + s];
        __syncthreads();
    }
    if (tid == 0) atomicAdd(&g_loss, (double)red[0]);
}

__global__ void k_finalize(float* out, int pos) {
    out[pos] = (float)(1.25 * g_loss / (double)NTENS);
}

// ---------------------------------------------------------------------------
extern "C" void kernel_launch(void* const* d_in, const int* in_sizes, int n_in,
                              void* d_out, int out_size) {
    const float* x   = (const float*)d_in[0];
    const float* emb = (const float*)d_in[1];
    float* out = (float*)d_out;

    cudaFuncSetAttribute(k_mma, cudaFuncAttributeMaxDynamicSharedMemorySize, SM_TOTAL);

    k_prepe<<<4, 256>>>(emb);
    k_split<<<1024, 256>>>(x);
    k_mma<<<NROWS / 128, 256, SM_TOTAL>>>();
    k_exact<<<592, 64>>>(emb);
    k_full<<<64, 256>>>(emb);

    int write_tensor = (out_size >= NTENS) ? 1 : 0;
    k_output<<<512, 256>>>(x, emb, out, write_tensor);

    if (out_size == NTENS + 1)      k_finalize<<<1, 1>>>(out, NTENS);
    else if (out_size == 1)         k_finalize<<<1, 1>>>(out, 0);
}